// round 13
// baseline (speedup 1.0000x reference)
#include <cuda_runtime.h>
#include <cuda_bf16.h>

// Problem constants (fixed by the reference)
constexpr int NN = 40000;   // nodes
constexpr int NE = 640000;  // edges
constexpr int DD = 128;     // feature dim
constexpr int NG = 64;      // graphs

constexpr int SCAN_B = 1024;
constexpr int NSCAN  = (NN + SCAN_B) / SCAN_B;  // 40 scan blocks; block 39 covers i=NN

constexpr int CSR_GRID = 148;   // exactly one wave on GB300 (152 SMs, 148 safe)
constexpr int CSR_THR  = 1024;

// ---------------- scratch (static device globals; no allocations) ----------------
__device__ __nv_bfloat16 g_hb [NN * DD];  // gemm1 out (unscaled, bf16)
__device__ __nv_bfloat16 g_x2b[NN * DD];  // agg1 out (dinv-prescaled relu, bf16)
__device__ float g_y  [NN * DD];          // agg2 out (fp32)
__device__ int   g_deg[NN];               // in-degree (zeroed by agg1 for next replay)
__device__ float g_dinv[NN];              // 1/sqrt(deg+1)
__device__ int   g_rowptr[NN + 1];        // CSR row pointers (by dst)
__device__ int   g_cnt[NN];               // fill cursors
__device__ int   g_csr[NE];               // CSR column indices (src node per edge)
__device__ int   g_bsum[64];              // scan block aggregates
__device__ volatile unsigned g_bar;       // grid barrier counter (zeroed by agg1)

// ---------------- packed f32x2 helpers ----------------
__device__ __forceinline__ unsigned long long pack2(float lo, float hi) {
    unsigned long long r;
    asm("mov.b64 %0, {%1, %2};" : "=l"(r) : "f"(lo), "f"(hi));
    return r;
}
__device__ __forceinline__ void unpack2(unsigned long long v, float& lo, float& hi) {
    asm("mov.b64 {%0, %1}, %2;" : "=f"(lo), "=f"(hi) : "l"(v));
}
__device__ __forceinline__ unsigned long long fma2(unsigned long long a,
                                                   unsigned long long b,
                                                   unsigned long long c) {
    unsigned long long d;
    asm("fma.rn.f32x2 %0, %1, %2, %3;" : "=l"(d) : "l"(a), "l"(b), "l"(c));
    return d;
}

// ---------------- bf16x4 helpers ----------------
__device__ __forceinline__ float4 bf4_to_f4(uint2 p) {
    __nv_bfloat162 a = *reinterpret_cast<__nv_bfloat162*>(&p.x);
    __nv_bfloat162 b = *reinterpret_cast<__nv_bfloat162*>(&p.y);
    float2 f0 = __bfloat1622float2(a);
    float2 f1 = __bfloat1622float2(b);
    return make_float4(f0.x, f0.y, f1.x, f1.y);
}
__device__ __forceinline__ uint2 f4_to_bf4(float4 v) {
    __nv_bfloat162 a = __float22bfloat162_rn(make_float2(v.x, v.y));
    __nv_bfloat162 b = __float22bfloat162_rn(make_float2(v.z, v.w));
    uint2 r;
    r.x = *reinterpret_cast<unsigned*>(&a);
    r.y = *reinterpret_cast<unsigned*>(&b);
    return r;
}

// ---------------- fused CSR construction (one launch, 3 grid barriers) ----
// All CSR_GRID blocks are co-resident (one wave), so spinning is safe.
__device__ __forceinline__ void grid_barrier(unsigned target) {
    __syncthreads();
    if (threadIdx.x == 0) {
        __threadfence();
        atomicAdd((unsigned*)&g_bar, 1u);
        while (g_bar < target) { }
        __threadfence();
    }
    __syncthreads();
}

__global__ void __launch_bounds__(CSR_THR) csr_kernel(const int4* __restrict__ src4,
                                                      const int4* __restrict__ dst4) {
    int tid = threadIdx.x, lane = tid & 31, wid = tid >> 5;
    int b = blockIdx.x;
    int gtid = b * CSR_THR + tid;
    constexpr int GSTRIDE = CSR_GRID * CSR_THR;
    constexpr int NE4 = NE / 4;

    // ---- phase 1: degree histogram ----
    for (int i = gtid; i < NE4; i += GSTRIDE) {
        int4 d = dst4[i];
        atomicAdd(&g_deg[d.x], 1);
        atomicAdd(&g_deg[d.y], 1);
        atomicAdd(&g_deg[d.z], 1);
        atomicAdd(&g_deg[d.w], 1);
    }
    grid_barrier(CSR_GRID);

    // ---- phase 2a: per-block inclusive scan + block sums (blocks 0..NSCAN-1) ----
    __shared__ int wsum[32];
    __shared__ int s_off;
    int i = b * SCAN_B + tid;
    int v = 0, inc = 0, excl_local = 0;
    if (b < NSCAN) {
        v = (i < NN) ? g_deg[i] : 0;
        inc = v;
#pragma unroll
        for (int off = 1; off < 32; off <<= 1) {
            int n = __shfl_up_sync(0xFFFFFFFFu, inc, off);
            if (lane >= off) inc += n;
        }
        if (lane == 31) wsum[wid] = inc;
        __syncthreads();
        if (wid == 0) {
            int s = wsum[lane];
            int si = s;
#pragma unroll
            for (int off = 1; off < 32; off <<= 1) {
                int n = __shfl_up_sync(0xFFFFFFFFu, si, off);
                if (lane >= off) si += n;
            }
            if (lane == 31) g_bsum[b] = si;
            wsum[lane] = si - s;  // exclusive warp offsets
        }
        __syncthreads();
        excl_local = inc - v + wsum[wid];
    }
    grid_barrier(2 * CSR_GRID);

    // ---- phase 2b: add cross-block offsets, write rowptr/cnt/dinv ----
    if (b < NSCAN) {
        if (wid == 0) {
            int a = (lane < b) ? g_bsum[lane] : 0;
            if (lane + 32 < b) a += g_bsum[lane + 32];
#pragma unroll
            for (int off = 16; off; off >>= 1)
                a += __shfl_down_sync(0xFFFFFFFFu, a, off);
            if (lane == 0) s_off = a;
        }
        __syncthreads();
        int excl = excl_local + s_off;
        if (i <= NN) {
            g_rowptr[i] = excl;
            if (i < NN) {
                g_cnt[i]  = excl;
                g_dinv[i] = rsqrtf((float)(v + 1));  // +1: self loop
            }
        }
    }
    grid_barrier(3 * CSR_GRID);

    // ---- phase 3: fill CSR ----
    for (int e = gtid; e < NE4; e += GSTRIDE) {
        int4 s = src4[e];
        int4 d = dst4[e];
        int p0 = atomicAdd(&g_cnt[d.x], 1);
        int p1 = atomicAdd(&g_cnt[d.y], 1);
        int p2 = atomicAdd(&g_cnt[d.z], 1);
        int p3 = atomicAdd(&g_cnt[d.w], 1);
        g_csr[p0] = s.x;
        g_csr[p1] = s.y;
        g_csr[p2] = s.z;
        g_csr[p3] = s.w;
    }
}

// ---------------- GEMM-1: g_hb = bf16(x @ W1) ----------------
// R4-proven config: 128x128 tile, 256 threads, 8x8/thread, f32x2 mainloop.
__global__ void __launch_bounds__(256) gemm_kernel(const float* __restrict__ A,
                                                   const float* __restrict__ W) {
    __shared__ float As[16][132];
    __shared__ float Bs[16][128];

    int tid = threadIdx.x;
    int tx = tid & 15;
    int ty = tid >> 4;
    int rowBase = blockIdx.x * 128;

    unsigned long long acc2[8][4];
#pragma unroll
    for (int i = 0; i < 8; i++)
#pragma unroll
        for (int j = 0; j < 4; j++) acc2[i][j] = 0ull;

    for (int kt = 0; kt < 128; kt += 16) {
#pragma unroll
        for (int l = 0; l < 2; l++) {
            int idx = tid + l * 256;
            int r   = idx >> 2;
            int k4  = (idx & 3) << 2;
            float4 v = make_float4(0.f, 0.f, 0.f, 0.f);
            int gr = rowBase + r;
            if (gr < NN) v = *(const float4*)(A + gr * 128 + kt + k4);
            As[k4 + 0][r] = v.x;
            As[k4 + 1][r] = v.y;
            As[k4 + 2][r] = v.z;
            As[k4 + 3][r] = v.w;
        }
#pragma unroll
        for (int l = 0; l < 2; l++) {
            int idx = tid + l * 256;
            int kk  = idx >> 5;
            int n4  = (idx & 31) << 2;
            *(float4*)&Bs[kk][n4] = *(const float4*)(W + (kt + kk) * 128 + n4);
        }
        __syncthreads();

#pragma unroll
        for (int k = 0; k < 16; k++) {
            float4 a0 = *(const float4*)&As[k][ty * 8];
            float4 a1 = *(const float4*)&As[k][ty * 8 + 4];
            unsigned long long ad[8];
            ad[0] = pack2(a0.x, a0.x); ad[1] = pack2(a0.y, a0.y);
            ad[2] = pack2(a0.z, a0.z); ad[3] = pack2(a0.w, a0.w);
            ad[4] = pack2(a1.x, a1.x); ad[5] = pack2(a1.y, a1.y);
            ad[6] = pack2(a1.z, a1.z); ad[7] = pack2(a1.w, a1.w);
            ulonglong2 bp0 = *(const ulonglong2*)&Bs[k][tx * 4];
            ulonglong2 bp1 = *(const ulonglong2*)&Bs[k][tx * 4 + 64];
            unsigned long long bd[4] = {bp0.x, bp0.y, bp1.x, bp1.y};
#pragma unroll
            for (int i = 0; i < 8; i++)
#pragma unroll
                for (int j = 0; j < 4; j++)
                    acc2[i][j] = fma2(ad[i], bd[j], acc2[i][j]);
        }
        __syncthreads();
    }

#pragma unroll
    for (int i = 0; i < 8; i++) {
        int gr = rowBase + ty * 8 + i;
        if (gr < NN) {
            float o[8];
#pragma unroll
            for (int j = 0; j < 4; j++) {
                float lo, hi;
                unpack2(acc2[i][j], lo, hi);
                o[2 * j]     = lo;
                o[2 * j + 1] = hi;
            }
            uint2 p0 = f4_to_bf4(make_float4(o[0], o[1], o[2], o[3]));
            uint2 p1 = f4_to_bf4(make_float4(o[4], o[5], o[6], o[7]));
            *(uint2*)(g_hb + gr * 128 + tx * 4)      = p0;
            *(uint2*)(g_hb + gr * 128 + tx * 4 + 64) = p1;
        }
    }
}

// ---------------- aggregation: warp per node, bf16 gathers, 8-deep MLP ----
// LAYER==1: in = g_hb. x2 = relu(dinv_i*(dinv_i*h_i + sum dinv_j*h_j) + b1),
//           stores bf16(dinv_i * x2). Also re-zeros g_deg/g_bar for the
//           next graph replay (their last readers have completed).
// LAYER==2: in = g_x2b (pre-scaled). y_i = dinv_i*(x2s_i + sum x2s_j) -> g_y.
template <int LAYER>
__global__ void __launch_bounds__(256) agg_kernel(const float* __restrict__ bias) {
    int t = blockIdx.x * blockDim.x + threadIdx.x;
    if (LAYER == 1) {
        // maintain zero-invariant for next replay (deg, grid-barrier counter)
        if (t < NN) g_deg[t] = 0;
        if (t == 0) g_bar = 0;
    }
    int w    = t >> 5;
    int lane = threadIdx.x & 31;
    if (w >= NN) return;

    int beg = g_rowptr[w];
    int end = g_rowptr[w + 1];
    float dv = g_dinv[w];

    const uint2* hv = (LAYER == 1) ? (const uint2*)g_hb : (const uint2*)g_x2b;
    float4 self = bf4_to_f4(hv[w * 32 + lane]);
    float4 acc;
    if (LAYER == 1) {
        acc = make_float4(self.x * dv, self.y * dv, self.z * dv, self.w * dv);
    } else {
        acc = self;
    }

    int k = beg;
    // 8-deep: 8 independent gathers in flight per iteration
    for (; k + 7 < end; k += 8) {
        int sx[8];
#pragma unroll
        for (int u = 0; u < 8; u++) sx[u] = g_csr[k + u];
        uint2 px[8];
#pragma unroll
        for (int u = 0; u < 8; u++) px[u] = hv[sx[u] * 32 + lane];
        if (LAYER == 1) {
            float dx[8];
#pragma unroll
            for (int u = 0; u < 8; u++) dx[u] = __ldg(&g_dinv[sx[u]]);
#pragma unroll
            for (int u = 0; u < 8; u++) {
                float4 vv = bf4_to_f4(px[u]);
                acc.x = fmaf(vv.x, dx[u], acc.x);
                acc.y = fmaf(vv.y, dx[u], acc.y);
                acc.z = fmaf(vv.z, dx[u], acc.z);
                acc.w = fmaf(vv.w, dx[u], acc.w);
            }
        } else {
#pragma unroll
            for (int u = 0; u < 8; u++) {
                float4 vv = bf4_to_f4(px[u]);
                acc.x += vv.x; acc.y += vv.y; acc.z += vv.z; acc.w += vv.w;
            }
        }
    }
    // remainder
    for (; k < end; k++) {
        int s = g_csr[k];
        float4 vv = bf4_to_f4(hv[s * 32 + lane]);
        if (LAYER == 1) {
            float d = __ldg(&g_dinv[s]);
            acc.x = fmaf(vv.x, d, acc.x); acc.y = fmaf(vv.y, d, acc.y);
            acc.z = fmaf(vv.z, d, acc.z); acc.w = fmaf(vv.w, d, acc.w);
        } else {
            acc.x += vv.x; acc.y += vv.y; acc.z += vv.z; acc.w += vv.w;
        }
    }

    if (LAYER == 1) {
        float4 bb = ((const float4*)bias)[lane];
        float4 r;
        r.x = fmaf(dv, acc.x, bb.x);
        r.y = fmaf(dv, acc.y, bb.y);
        r.z = fmaf(dv, acc.z, bb.z);
        r.w = fmaf(dv, acc.w, bb.w);
        r.x = fmaxf(r.x, 0.f) * dv;
        r.y = fmaxf(r.y, 0.f) * dv;
        r.z = fmaxf(r.z, 0.f) * dv;
        r.w = fmaxf(r.w, 0.f) * dv;
        ((uint2*)g_x2b)[w * 32 + lane] = f4_to_bf4(r);
    } else {
        float4 r = make_float4(dv * acc.x, dv * acc.y, dv * acc.z, dv * acc.w);
        ((float4*)g_y)[w * 32 + lane] = r;
    }
}

// ---------------- fused pool + out-GEMM: one block per graph ----------------
// out[g] = mean_{i in graph g}(y_i) @ W2 + b2   (empty graph -> 0)
__device__ __forceinline__ int lower_bound_dev(const int* a, int n, int key) {
    int lo = 0, hi = n;
    while (lo < hi) {
        int mid = (lo + hi) >> 1;
        if (a[mid] < key) lo = mid + 1; else hi = mid;
    }
    return lo;
}

__global__ void __launch_bounds__(512) poolout_kernel(const int* __restrict__ batch,
                                                      const float* __restrict__ W2,
                                                      const float* __restrict__ b2,
                                                      float* __restrict__ out) {
    __shared__ float zrow[128];
    __shared__ float red[4][128];
    __shared__ int s_lo, s_hi;
    int g = blockIdx.x;
    int t = threadIdx.x;
    int f   = t & 127;   // feature
    int seg = t >> 7;    // slice 0..3
    if (t == 0) {
        s_lo = lower_bound_dev(batch, NN, g);
        s_hi = lower_bound_dev(batch, NN, g + 1);
    }
    __syncthreads();
    int lo = s_lo, hi = s_hi;
    // pool
    float sum = 0.f;
    for (int r = lo + seg; r < hi; r += 4) sum += g_y[r * 128 + f];
    red[seg][f] = sum;
    __syncthreads();
    if (seg == 0) {
        float c = (float)(hi - lo);
        zrow[f] = (red[0][f] + red[1][f] + red[2][f] + red[3][f]) / fmaxf(c, 1.0f);
    }
    __syncthreads();
    // gemm: 4-way k-split dot with W2
    float acc = 0.f;
    int k0 = seg * 32;
#pragma unroll
    for (int kk = 0; kk < 32; kk++) {
        int k = k0 + kk;
        acc = fmaf(zrow[k], W2[k * 128 + f], acc);
    }
    red[seg][f] = acc;
    __syncthreads();
    if (seg == 0) {
        float r = (hi > lo)
                ? (red[0][f] + red[1][f] + red[2][f] + red[3][f] + b2[f])
                : 0.0f;   // empty graph: reference yields exactly 0
        out[g * 128 + f] = r;
    }
}

// ---------------- launch ----------------
extern "C" void kernel_launch(void* const* d_in, const int* in_sizes, int n_in,
                              void* d_out, int out_size) {
    const float* x     = (const float*)d_in[0];
    const int*   ei    = (const int*)d_in[1];   // [2, E] row-major
    const int*   batch = (const int*)d_in[2];
    const float* W1    = (const float*)d_in[3];
    const float* b1    = (const float*)d_in[4];
    const float* W2    = (const float*)d_in[5];
    const float* b2    = (const float*)d_in[6];
    float* out = (float*)d_out;

    const int4* src4 = (const int4*)ei;          // edge_index[0]
    const int4* dst4 = (const int4*)(ei + NE);   // edge_index[1] (16B-aligned: NE%4==0)

    // One-time host resources (streams/events are not device memory).
    static cudaStream_t s2 = nullptr;
    static cudaEvent_t evFork = nullptr, evJoin = nullptr;
    if (s2 == nullptr) {
        cudaStreamCreateWithFlags(&s2, cudaStreamNonBlocking);
        cudaEventCreateWithFlags(&evFork, cudaEventDisableTiming);
        cudaEventCreateWithFlags(&evJoin, cudaEventDisableTiming);
    }

    // Fork: GEMM-1 (no dependence on edges/dinv) runs on s2 while the fused
    // CSR build runs on the main stream.
    cudaEventRecord(evFork, 0);
    cudaStreamWaitEvent(s2, evFork, 0);
    gemm_kernel<<<(NN + 127) / 128, 256, 0, s2>>>(x, W1);
    cudaEventRecord(evJoin, s2);

    // Fused CSR build (hist + scan + fill in one launch; g_deg/g_bar are zero
    // on entry — zero-init on first call, re-zeroed by agg1 every call).
    csr_kernel<<<CSR_GRID, CSR_THR>>>(src4, dst4);

    // Join: aggregation needs both GEMM-1 output and the CSR.
    cudaStreamWaitEvent(0, evJoin, 0);

    // Layer 1 aggregation (+relu, +b1), writes dinv-prescaled bf16 x2.
    agg_kernel<1><<<(NN + 7) / 8, 256>>>(b1);

    // Layer 2 aggregation only (W2 commuted past S and pooling), writes g_y.
    agg_kernel<2><<<(NN + 7) / 8, 256>>>(nullptr);

    // Fused global-mean-pool + (z @ W2 + b2)
    poolout_kernel<<<NG, 512>>>(batch, W2, b2, out);
}

// round 14
// speedup vs baseline: 1.1056x; 1.1056x over previous
#include <cuda_runtime.h>
#include <cuda_bf16.h>

// Problem constants (fixed by the reference)
constexpr int NN = 40000;   // nodes
constexpr int NE = 640000;  // edges
constexpr int DD = 128;     // feature dim
constexpr int NG = 64;      // graphs

constexpr int SCAN_B = 1024;
constexpr int NSCAN  = (NN + SCAN_B) / SCAN_B;  // 40 blocks, block 39 covers i=NN

// ---------------- scratch (static device globals; no allocations) ----------------
__device__ __nv_bfloat16 g_hb [NN * DD];  // gemm1 out (unscaled, bf16)
__device__ __nv_bfloat16 g_x2b[NN * DD];  // agg1 out (dinv-prescaled relu, bf16)
__device__ float g_y  [NN * DD];          // agg2 out (fp32)
__device__ int   g_deg[NN];               // in-degree (zeroed by agg1 for next replay)
__device__ float g_dinv[NN];              // 1/sqrt(deg+1)
__device__ int   g_rowptr[NN + 1];        // CSR row pointers (by dst)
__device__ int   g_cnt[NN];               // fill cursors
__device__ int   g_csr[NE];               // CSR column indices (src node per edge)
__device__ int   g_bsum[64];              // scan block aggregates
__device__ int   g_flagv[64];             // scan lookback flags (zeroed by agg1)

// ---------------- packed f32x2 helpers ----------------
__device__ __forceinline__ unsigned long long pack2(float lo, float hi) {
    unsigned long long r;
    asm("mov.b64 %0, {%1, %2};" : "=l"(r) : "f"(lo), "f"(hi));
    return r;
}
__device__ __forceinline__ void unpack2(unsigned long long v, float& lo, float& hi) {
    asm("mov.b64 {%0, %1}, %2;" : "=f"(lo), "=f"(hi) : "l"(v));
}
__device__ __forceinline__ unsigned long long fma2(unsigned long long a,
                                                   unsigned long long b,
                                                   unsigned long long c) {
    unsigned long long d;
    asm("fma.rn.f32x2 %0, %1, %2, %3;" : "=l"(d) : "l"(a), "l"(b), "l"(c));
    return d;
}
__device__ __forceinline__ unsigned long long add2(unsigned long long a,
                                                   unsigned long long b) {
    unsigned long long d;
    asm("add.rn.f32x2 %0, %1, %2;" : "=l"(d) : "l"(a), "l"(b));
    return d;
}
__device__ __forceinline__ unsigned long long mul2(unsigned long long a,
                                                   unsigned long long b) {
    unsigned long long d;
    asm("mul.rn.f32x2 %0, %1, %2;" : "=l"(d) : "l"(a), "l"(b));
    return d;
}

// bf16x2 word -> packed f32x2 u64 (f32(bf16) == bf16 << 16; 2 alu ops)
__device__ __forceinline__ unsigned long long bfw_to_pk(unsigned u) {
    unsigned lo = u << 16;
    unsigned hi = u & 0xFFFF0000u;
    unsigned long long o;
    asm("mov.b64 %0, {%1, %2};" : "=l"(o) : "r"(lo), "r"(hi));
    return o;
}

// ---------------- bf16x4 helpers (store path) ----------------
__device__ __forceinline__ uint2 f4_to_bf4(float4 v) {
    __nv_bfloat162 a = __float22bfloat162_rn(make_float2(v.x, v.y));
    __nv_bfloat162 b = __float22bfloat162_rn(make_float2(v.z, v.w));
    uint2 r;
    r.x = *reinterpret_cast<unsigned*>(&a);
    r.y = *reinterpret_cast<unsigned*>(&b);
    return r;
}

// ---------------- CSR construction (R11-proven shape) ----------------
__global__ void hist_kernel(const int* __restrict__ dst) {
    int i = blockIdx.x * blockDim.x + threadIdx.x;
    if (i < NE) atomicAdd(&g_deg[dst[i]], 1);
}

// Single-pass scan with decoupled lookback (40 blocks, all co-resident in
// wave 1 so cross-block spinning is safe). Writes rowptr, fill cursors,
// dinv. Flags/bsum zeroed by previous replay's agg1.
__global__ void __launch_bounds__(SCAN_B) scan_kernel() {
    __shared__ int wsum[32];
    __shared__ int s_off;
    int tid = threadIdx.x, lane = tid & 31, wid = tid >> 5;
    int b = blockIdx.x;
    int i = b * SCAN_B + tid;
    int v = (i < NN) ? g_deg[i] : 0;
    int inc = v;
#pragma unroll
    for (int off = 1; off < 32; off <<= 1) {
        int n = __shfl_up_sync(0xFFFFFFFFu, inc, off);
        if (lane >= off) inc += n;
    }
    if (lane == 31) wsum[wid] = inc;
    __syncthreads();
    if (wid == 0) {
        int s = wsum[lane];
        int si = s;
#pragma unroll
        for (int off = 1; off < 32; off <<= 1) {
            int n = __shfl_up_sync(0xFFFFFFFFu, si, off);
            if (lane >= off) si += n;
        }
        int total = __shfl_sync(0xFFFFFFFFu, si, 31);
        if (lane == 0) {
            g_bsum[b] = total;
            __threadfence();
            *(volatile int*)&g_flagv[b] = 1;
        }
        wsum[lane] = si - s;  // exclusive warp offsets
        int a = 0;
        if (b > 0) {
            bool n0 = lane < b;
            bool n1 = lane + 32 < b;
            volatile int* fl = (volatile int*)g_flagv;
            while (true) {
                int f0 = n0 ? fl[lane] : 1;
                int f1 = n1 ? fl[lane + 32] : 1;
                if (__all_sync(0xFFFFFFFFu, (f0 != 0) && (f1 != 0))) break;
            }
            __threadfence();
            a = (n0 ? g_bsum[lane] : 0) + (n1 ? g_bsum[lane + 32] : 0);
#pragma unroll
            for (int off = 16; off; off >>= 1)
                a += __shfl_down_sync(0xFFFFFFFFu, a, off);
        }
        if (lane == 0) s_off = a;
    }
    __syncthreads();
    int excl = inc - v + wsum[wid] + s_off;
    if (i <= NN) {
        g_rowptr[i] = excl;
        if (i < NN) {
            g_cnt[i]  = excl;
            g_dinv[i] = rsqrtf((float)(v + 1));  // +1: self loop
        }
    }
}

__global__ void fill_kernel(const int* __restrict__ src, const int* __restrict__ dst) {
    int i = blockIdx.x * blockDim.x + threadIdx.x;
    if (i < NE) {
        int slot = atomicAdd(&g_cnt[dst[i]], 1);
        g_csr[slot] = src[i];
    }
}

// ---------------- GEMM-1: g_hb = bf16(x @ W1) ----------------
// R4-proven config: 128x128 tile, 256 threads, 8x8/thread, f32x2 mainloop.
__global__ void __launch_bounds__(256) gemm_kernel(const float* __restrict__ A,
                                                   const float* __restrict__ W) {
    __shared__ float As[16][132];
    __shared__ float Bs[16][128];

    int tid = threadIdx.x;
    int tx = tid & 15;
    int ty = tid >> 4;
    int rowBase = blockIdx.x * 128;

    unsigned long long acc2[8][4];
#pragma unroll
    for (int i = 0; i < 8; i++)
#pragma unroll
        for (int j = 0; j < 4; j++) acc2[i][j] = 0ull;

    for (int kt = 0; kt < 128; kt += 16) {
#pragma unroll
        for (int l = 0; l < 2; l++) {
            int idx = tid + l * 256;
            int r   = idx >> 2;
            int k4  = (idx & 3) << 2;
            float4 v = make_float4(0.f, 0.f, 0.f, 0.f);
            int gr = rowBase + r;
            if (gr < NN) v = *(const float4*)(A + gr * 128 + kt + k4);
            As[k4 + 0][r] = v.x;
            As[k4 + 1][r] = v.y;
            As[k4 + 2][r] = v.z;
            As[k4 + 3][r] = v.w;
        }
#pragma unroll
        for (int l = 0; l < 2; l++) {
            int idx = tid + l * 256;
            int kk  = idx >> 5;
            int n4  = (idx & 31) << 2;
            *(float4*)&Bs[kk][n4] = *(const float4*)(W + (kt + kk) * 128 + n4);
        }
        __syncthreads();

#pragma unroll
        for (int k = 0; k < 16; k++) {
            float4 a0 = *(const float4*)&As[k][ty * 8];
            float4 a1 = *(const float4*)&As[k][ty * 8 + 4];
            unsigned long long ad[8];
            ad[0] = pack2(a0.x, a0.x); ad[1] = pack2(a0.y, a0.y);
            ad[2] = pack2(a0.z, a0.z); ad[3] = pack2(a0.w, a0.w);
            ad[4] = pack2(a1.x, a1.x); ad[5] = pack2(a1.y, a1.y);
            ad[6] = pack2(a1.z, a1.z); ad[7] = pack2(a1.w, a1.w);
            ulonglong2 bp0 = *(const ulonglong2*)&Bs[k][tx * 4];
            ulonglong2 bp1 = *(const ulonglong2*)&Bs[k][tx * 4 + 64];
            unsigned long long bd[4] = {bp0.x, bp0.y, bp1.x, bp1.y};
#pragma unroll
            for (int i = 0; i < 8; i++)
#pragma unroll
                for (int j = 0; j < 4; j++)
                    acc2[i][j] = fma2(ad[i], bd[j], acc2[i][j]);
        }
        __syncthreads();
    }

#pragma unroll
    for (int i = 0; i < 8; i++) {
        int gr = rowBase + ty * 8 + i;
        if (gr < NN) {
            float o[8];
#pragma unroll
            for (int j = 0; j < 4; j++) {
                float lo, hi;
                unpack2(acc2[i][j], lo, hi);
                o[2 * j]     = lo;
                o[2 * j + 1] = hi;
            }
            uint2 p0 = f4_to_bf4(make_float4(o[0], o[1], o[2], o[3]));
            uint2 p1 = f4_to_bf4(make_float4(o[4], o[5], o[6], o[7]));
            *(uint2*)(g_hb + gr * 128 + tx * 4)      = p0;
            *(uint2*)(g_hb + gr * 128 + tx * 4 + 64) = p1;
        }
    }
}

// ---------------- aggregation: warp per node, bf16 gathers, 8-deep MLP,
//                  packed f32x2 accumulation ----------------
// LAYER==1: in = g_hb. x2 = relu(dinv_i*(dinv_i*h_i + sum dinv_j*h_j) + b1),
//           stores bf16(dinv_i * x2). Also re-zeros g_deg/g_flagv for the
//           next graph replay (their last readers have completed).
// LAYER==2: in = g_x2b (pre-scaled). y_i = dinv_i*(x2s_i + sum x2s_j) -> g_y.
template <int LAYER>
__global__ void __launch_bounds__(256) agg_kernel(const float* __restrict__ bias) {
    int t = blockIdx.x * blockDim.x + threadIdx.x;
    if (LAYER == 1) {
        // maintain zero-invariant for next replay (deg, lookback flags)
        if (t < NN) g_deg[t] = 0;
        if (t < 64) g_flagv[t] = 0;
    }
    int w    = t >> 5;
    int lane = threadIdx.x & 31;
    if (w >= NN) return;

    int beg = g_rowptr[w];
    int end = g_rowptr[w + 1];
    float dv = g_dinv[w];

    const uint2* hv = (LAYER == 1) ? (const uint2*)g_hb : (const uint2*)g_x2b;

    // self-loop term (packed accumulators: acc0 = (x,y), acc1 = (z,w))
    uint2 sp = hv[w * 32 + lane];
    unsigned long long acc0 = bfw_to_pk(sp.x);
    unsigned long long acc1 = bfw_to_pk(sp.y);
    if (LAYER == 1) {
        unsigned long long dd = pack2(dv, dv);
        acc0 = mul2(acc0, dd);
        acc1 = mul2(acc1, dd);
    }

    int k = beg;
    // 8-deep: 8 independent gathers in flight per iteration
    for (; k + 7 < end; k += 8) {
        int sx[8];
#pragma unroll
        for (int u = 0; u < 8; u++) sx[u] = g_csr[k + u];
        uint2 px[8];
#pragma unroll
        for (int u = 0; u < 8; u++) px[u] = hv[sx[u] * 32 + lane];
        if (LAYER == 1) {
            float dx[8];
#pragma unroll
            for (int u = 0; u < 8; u++) dx[u] = __ldg(&g_dinv[sx[u]]);
#pragma unroll
            for (int u = 0; u < 8; u++) {
                unsigned long long dd = pack2(dx[u], dx[u]);
                acc0 = fma2(bfw_to_pk(px[u].x), dd, acc0);
                acc1 = fma2(bfw_to_pk(px[u].y), dd, acc1);
            }
        } else {
#pragma unroll
            for (int u = 0; u < 8; u++) {
                acc0 = add2(bfw_to_pk(px[u].x), acc0);
                acc1 = add2(bfw_to_pk(px[u].y), acc1);
            }
        }
    }
    // remainder
    for (; k < end; k++) {
        int s = g_csr[k];
        uint2 p = hv[s * 32 + lane];
        if (LAYER == 1) {
            float d = __ldg(&g_dinv[s]);
            unsigned long long dd = pack2(d, d);
            acc0 = fma2(bfw_to_pk(p.x), dd, acc0);
            acc1 = fma2(bfw_to_pk(p.y), dd, acc1);
        } else {
            acc0 = add2(bfw_to_pk(p.x), acc0);
            acc1 = add2(bfw_to_pk(p.y), acc1);
        }
    }

    float4 acc;
    unpack2(acc0, acc.x, acc.y);
    unpack2(acc1, acc.z, acc.w);

    if (LAYER == 1) {
        float4 bb = ((const float4*)bias)[lane];
        float4 r;
        r.x = fmaf(dv, acc.x, bb.x);
        r.y = fmaf(dv, acc.y, bb.y);
        r.z = fmaf(dv, acc.z, bb.z);
        r.w = fmaf(dv, acc.w, bb.w);
        r.x = fmaxf(r.x, 0.f) * dv;
        r.y = fmaxf(r.y, 0.f) * dv;
        r.z = fmaxf(r.z, 0.f) * dv;
        r.w = fmaxf(r.w, 0.f) * dv;
        ((uint2*)g_x2b)[w * 32 + lane] = f4_to_bf4(r);
    } else {
        float4 r = make_float4(dv * acc.x, dv * acc.y, dv * acc.z, dv * acc.w);
        ((float4*)g_y)[w * 32 + lane] = r;
    }
}

// ---------------- fused pool + out-GEMM: one block per graph ----------------
// out[g] = mean_{i in graph g}(y_i) @ W2 + b2   (empty graph -> 0)
__device__ __forceinline__ int lower_bound_dev(const int* a, int n, int key) {
    int lo = 0, hi = n;
    while (lo < hi) {
        int mid = (lo + hi) >> 1;
        if (a[mid] < key) lo = mid + 1; else hi = mid;
    }
    return lo;
}

__global__ void __launch_bounds__(512) poolout_kernel(const int* __restrict__ batch,
                                                      const float* __restrict__ W2,
                                                      const float* __restrict__ b2,
                                                      float* __restrict__ out) {
    __shared__ float zrow[128];
    __shared__ float red[4][128];
    __shared__ int s_lo, s_hi;
    int g = blockIdx.x;
    int t = threadIdx.x;
    int f   = t & 127;   // feature
    int seg = t >> 7;    // slice 0..3
    if (t == 0) {
        s_lo = lower_bound_dev(batch, NN, g);
        s_hi = lower_bound_dev(batch, NN, g + 1);
    }
    __syncthreads();
    int lo = s_lo, hi = s_hi;
    // pool
    float sum = 0.f;
    for (int r = lo + seg; r < hi; r += 4) sum += g_y[r * 128 + f];
    red[seg][f] = sum;
    __syncthreads();
    if (seg == 0) {
        float c = (float)(hi - lo);
        zrow[f] = (red[0][f] + red[1][f] + red[2][f] + red[3][f]) / fmaxf(c, 1.0f);
    }
    __syncthreads();
    // gemm: 4-way k-split dot with W2
    float acc = 0.f;
    int k0 = seg * 32;
#pragma unroll
    for (int kk = 0; kk < 32; kk++) {
        int k = k0 + kk;
        acc = fmaf(zrow[k], W2[k * 128 + f], acc);
    }
    red[seg][f] = acc;
    __syncthreads();
    if (seg == 0) {
        float r = (hi > lo)
                ? (red[0][f] + red[1][f] + red[2][f] + red[3][f] + b2[f])
                : 0.0f;   // empty graph: reference yields exactly 0
        out[g * 128 + f] = r;
    }
}

// ---------------- launch ----------------
extern "C" void kernel_launch(void* const* d_in, const int* in_sizes, int n_in,
                              void* d_out, int out_size) {
    const float* x     = (const float*)d_in[0];
    const int*   ei    = (const int*)d_in[1];   // [2, E] row-major
    const int*   batch = (const int*)d_in[2];
    const float* W1    = (const float*)d_in[3];
    const float* b1    = (const float*)d_in[4];
    const float* W2    = (const float*)d_in[5];
    const float* b2    = (const float*)d_in[6];
    float* out = (float*)d_out;

    const int* src = ei;        // edge_index[0]
    const int* dst = ei + NE;   // edge_index[1]

    // One-time host resources (streams/events are not device memory).
    static cudaStream_t s2 = nullptr;
    static cudaEvent_t evFork = nullptr, evJoin = nullptr;
    if (s2 == nullptr) {
        cudaStreamCreateWithFlags(&s2, cudaStreamNonBlocking);
        cudaEventCreateWithFlags(&evFork, cudaEventDisableTiming);
        cudaEventCreateWithFlags(&evJoin, cudaEventDisableTiming);
    }

    // Fork: GEMM-1 (no dependence on edges/dinv) runs on s2 while the CSR
    // build runs on the main stream.
    cudaEventRecord(evFork, 0);
    cudaStreamWaitEvent(s2, evFork, 0);
    gemm_kernel<<<(NN + 127) / 128, 256, 0, s2>>>(x, W1);
    cudaEventRecord(evJoin, s2);

    // CSR build (by destination) + dinv. g_deg and g_flagv are zero on entry
    // (zero-init on first call; re-zeroed by agg1 on every call).
    hist_kernel<<<(NE + 255) / 256, 256>>>(dst);
    scan_kernel<<<NSCAN, SCAN_B>>>();
    fill_kernel<<<(NE + 255) / 256, 256>>>(src, dst);

    // Join: aggregation needs both GEMM-1 output and the CSR.
    cudaStreamWaitEvent(0, evJoin, 0);

    // Layer 1 aggregation (+relu, +b1), writes dinv-prescaled bf16 x2.
    agg_kernel<1><<<(NN + 7) / 8, 256>>>(b1);

    // Layer 2 aggregation only (W2 commuted past S and pooling), writes g_y.
    agg_kernel<2><<<(NN + 7) / 8, 256>>>(nullptr);

    // Fused global-mean-pool + (z @ W2 + b2)
    poolout_kernel<<<NG, 512>>>(batch, W2, b2, out);
}

// round 15
// speedup vs baseline: 1.1071x; 1.0013x over previous
#include <cuda_runtime.h>
#include <cuda_bf16.h>

// Problem constants (fixed by the reference)
constexpr int NN = 40000;   // nodes
constexpr int NE = 640000;  // edges
constexpr int DD = 128;     // feature dim
constexpr int NG = 64;      // graphs

constexpr int SCAN_B = 1024;
constexpr int NSCAN  = (NN + SCAN_B) / SCAN_B;  // 40 blocks, block 39 covers i=NN

// ---------------- scratch (static device globals; no allocations) ----------------
__device__ __nv_bfloat16 g_hb [NN * DD];  // gemm1 out (unscaled, bf16)
__device__ __nv_bfloat16 g_x2b[NN * DD];  // agg1 out (dinv-prescaled relu, bf16)
__device__ float g_y  [NN * DD];          // agg2 out (fp32)
__device__ int   g_deg[NN];               // in-degree (zeroed by agg1 for next replay)
__device__ float g_dinv[NN];              // 1/sqrt(deg+1)
__device__ int   g_rowptr[NN + 1];        // CSR row pointers (by dst)
__device__ int   g_cnt[NN];               // fill cursors
__device__ int   g_csr[NE];               // CSR column indices (src node per edge)
__device__ int   g_bsum[64];              // scan block aggregates
__device__ int   g_flagv[64];             // scan lookback flags (zeroed by agg1)

// ---------------- packed f32x2 helpers ----------------
__device__ __forceinline__ unsigned long long pack2(float lo, float hi) {
    unsigned long long r;
    asm("mov.b64 %0, {%1, %2};" : "=l"(r) : "f"(lo), "f"(hi));
    return r;
}
__device__ __forceinline__ void unpack2(unsigned long long v, float& lo, float& hi) {
    asm("mov.b64 {%0, %1}, %2;" : "=f"(lo), "=f"(hi) : "l"(v));
}
__device__ __forceinline__ unsigned long long fma2(unsigned long long a,
                                                   unsigned long long b,
                                                   unsigned long long c) {
    unsigned long long d;
    asm("fma.rn.f32x2 %0, %1, %2, %3;" : "=l"(d) : "l"(a), "l"(b), "l"(c));
    return d;
}
__device__ __forceinline__ unsigned long long add2(unsigned long long a,
                                                   unsigned long long b) {
    unsigned long long d;
    asm("add.rn.f32x2 %0, %1, %2;" : "=l"(d) : "l"(a), "l"(b));
    return d;
}
__device__ __forceinline__ unsigned long long mul2(unsigned long long a,
                                                   unsigned long long b) {
    unsigned long long d;
    asm("mul.rn.f32x2 %0, %1, %2;" : "=l"(d) : "l"(a), "l"(b));
    return d;
}

// bf16x2 word -> packed f32x2 u64 (f32(bf16) == bf16 << 16; 2 alu ops)
__device__ __forceinline__ unsigned long long bfw_to_pk(unsigned u) {
    unsigned lo = u << 16;
    unsigned hi = u & 0xFFFF0000u;
    unsigned long long o;
    asm("mov.b64 %0, {%1, %2};" : "=l"(o) : "r"(lo), "r"(hi));
    return o;
}

// ---------------- bf16x4 helpers (store path) ----------------
__device__ __forceinline__ uint2 f4_to_bf4(float4 v) {
    __nv_bfloat162 a = __float22bfloat162_rn(make_float2(v.x, v.y));
    __nv_bfloat162 b = __float22bfloat162_rn(make_float2(v.z, v.w));
    uint2 r;
    r.x = *reinterpret_cast<unsigned*>(&a);
    r.y = *reinterpret_cast<unsigned*>(&b);
    return r;
}

// ---------------- CSR construction (R11-proven shape) ----------------
__global__ void hist_kernel(const int* __restrict__ dst) {
    int i = blockIdx.x * blockDim.x + threadIdx.x;
    if (i < NE) atomicAdd(&g_deg[dst[i]], 1);
}

// Single-pass scan with decoupled lookback (40 blocks, all co-resident in
// wave 1 so cross-block spinning is safe). Writes rowptr, fill cursors,
// dinv. Flags/bsum zeroed by previous replay's agg1.
__global__ void __launch_bounds__(SCAN_B) scan_kernel() {
    __shared__ int wsum[32];
    __shared__ int s_off;
    int tid = threadIdx.x, lane = tid & 31, wid = tid >> 5;
    int b = blockIdx.x;
    int i = b * SCAN_B + tid;
    int v = (i < NN) ? g_deg[i] : 0;
    int inc = v;
#pragma unroll
    for (int off = 1; off < 32; off <<= 1) {
        int n = __shfl_up_sync(0xFFFFFFFFu, inc, off);
        if (lane >= off) inc += n;
    }
    if (lane == 31) wsum[wid] = inc;
    __syncthreads();
    if (wid == 0) {
        int s = wsum[lane];
        int si = s;
#pragma unroll
        for (int off = 1; off < 32; off <<= 1) {
            int n = __shfl_up_sync(0xFFFFFFFFu, si, off);
            if (lane >= off) si += n;
        }
        int total = __shfl_sync(0xFFFFFFFFu, si, 31);
        if (lane == 0) {
            g_bsum[b] = total;
            __threadfence();
            *(volatile int*)&g_flagv[b] = 1;
        }
        wsum[lane] = si - s;  // exclusive warp offsets
        int a = 0;
        if (b > 0) {
            bool n0 = lane < b;
            bool n1 = lane + 32 < b;
            volatile int* fl = (volatile int*)g_flagv;
            while (true) {
                int f0 = n0 ? fl[lane] : 1;
                int f1 = n1 ? fl[lane + 32] : 1;
                if (__all_sync(0xFFFFFFFFu, (f0 != 0) && (f1 != 0))) break;
            }
            __threadfence();
            a = (n0 ? g_bsum[lane] : 0) + (n1 ? g_bsum[lane + 32] : 0);
#pragma unroll
            for (int off = 16; off; off >>= 1)
                a += __shfl_down_sync(0xFFFFFFFFu, a, off);
        }
        if (lane == 0) s_off = a;
    }
    __syncthreads();
    int excl = inc - v + wsum[wid] + s_off;
    if (i <= NN) {
        g_rowptr[i] = excl;
        if (i < NN) {
            g_cnt[i]  = excl;
            g_dinv[i] = rsqrtf((float)(v + 1));  // +1: self loop
        }
    }
}

__global__ void fill_kernel(const int* __restrict__ src, const int* __restrict__ dst) {
    int i = blockIdx.x * blockDim.x + threadIdx.x;
    if (i < NE) {
        int slot = atomicAdd(&g_cnt[dst[i]], 1);
        g_csr[slot] = src[i];
    }
}

// ---------------- GEMM-1: g_hb = bf16(x @ W1) ----------------
// R4-proven config: 128x128 tile, 256 threads, 8x8/thread, f32x2 mainloop.
__global__ void __launch_bounds__(256) gemm_kernel(const float* __restrict__ A,
                                                   const float* __restrict__ W) {
    __shared__ float As[16][132];
    __shared__ float Bs[16][128];

    int tid = threadIdx.x;
    int tx = tid & 15;
    int ty = tid >> 4;
    int rowBase = blockIdx.x * 128;

    unsigned long long acc2[8][4];
#pragma unroll
    for (int i = 0; i < 8; i++)
#pragma unroll
        for (int j = 0; j < 4; j++) acc2[i][j] = 0ull;

    for (int kt = 0; kt < 128; kt += 16) {
#pragma unroll
        for (int l = 0; l < 2; l++) {
            int idx = tid + l * 256;
            int r   = idx >> 2;
            int k4  = (idx & 3) << 2;
            float4 v = make_float4(0.f, 0.f, 0.f, 0.f);
            int gr = rowBase + r;
            if (gr < NN) v = *(const float4*)(A + gr * 128 + kt + k4);
            As[k4 + 0][r] = v.x;
            As[k4 + 1][r] = v.y;
            As[k4 + 2][r] = v.z;
            As[k4 + 3][r] = v.w;
        }
#pragma unroll
        for (int l = 0; l < 2; l++) {
            int idx = tid + l * 256;
            int kk  = idx >> 5;
            int n4  = (idx & 31) << 2;
            *(float4*)&Bs[kk][n4] = *(const float4*)(W + (kt + kk) * 128 + n4);
        }
        __syncthreads();

#pragma unroll
        for (int k = 0; k < 16; k++) {
            float4 a0 = *(const float4*)&As[k][ty * 8];
            float4 a1 = *(const float4*)&As[k][ty * 8 + 4];
            unsigned long long ad[8];
            ad[0] = pack2(a0.x, a0.x); ad[1] = pack2(a0.y, a0.y);
            ad[2] = pack2(a0.z, a0.z); ad[3] = pack2(a0.w, a0.w);
            ad[4] = pack2(a1.x, a1.x); ad[5] = pack2(a1.y, a1.y);
            ad[6] = pack2(a1.z, a1.z); ad[7] = pack2(a1.w, a1.w);
            ulonglong2 bp0 = *(const ulonglong2*)&Bs[k][tx * 4];
            ulonglong2 bp1 = *(const ulonglong2*)&Bs[k][tx * 4 + 64];
            unsigned long long bd[4] = {bp0.x, bp0.y, bp1.x, bp1.y};
#pragma unroll
            for (int i = 0; i < 8; i++)
#pragma unroll
                for (int j = 0; j < 4; j++)
                    acc2[i][j] = fma2(ad[i], bd[j], acc2[i][j]);
        }
        __syncthreads();
    }

#pragma unroll
    for (int i = 0; i < 8; i++) {
        int gr = rowBase + ty * 8 + i;
        if (gr < NN) {
            float o[8];
#pragma unroll
            for (int j = 0; j < 4; j++) {
                float lo, hi;
                unpack2(acc2[i][j], lo, hi);
                o[2 * j]     = lo;
                o[2 * j + 1] = hi;
            }
            uint2 p0 = f4_to_bf4(make_float4(o[0], o[1], o[2], o[3]));
            uint2 p1 = f4_to_bf4(make_float4(o[4], o[5], o[6], o[7]));
            *(uint2*)(g_hb + gr * 128 + tx * 4)      = p0;
            *(uint2*)(g_hb + gr * 128 + tx * 4 + 64) = p1;
        }
    }
}

// ---------------- aggregation: warp per node, bf16 gathers, 8-deep MLP,
//                  packed f32x2 accumulation ----------------
// LAYER==1: in = g_hb. x2 = relu(dinv_i*(dinv_i*h_i + sum dinv_j*h_j) + b1),
//           stores bf16(dinv_i * x2). Also re-zeros g_deg/g_flagv for the
//           next graph replay (their last readers have completed).
// LAYER==2: in = g_x2b (pre-scaled). y_i = dinv_i*(x2s_i + sum x2s_j) -> g_y.
template <int LAYER>
__global__ void __launch_bounds__(256) agg_kernel(const float* __restrict__ bias) {
    int t = blockIdx.x * blockDim.x + threadIdx.x;
    if (LAYER == 1) {
        // maintain zero-invariant for next replay (deg, lookback flags)
        if (t < NN) g_deg[t] = 0;
        if (t < 64) g_flagv[t] = 0;
    }
    int w    = t >> 5;
    int lane = threadIdx.x & 31;
    if (w >= NN) return;

    int beg = g_rowptr[w];
    int end = g_rowptr[w + 1];
    float dv = g_dinv[w];

    const uint2* hv = (LAYER == 1) ? (const uint2*)g_hb : (const uint2*)g_x2b;

    // self-loop term (packed accumulators: acc0 = (x,y), acc1 = (z,w))
    uint2 sp = hv[w * 32 + lane];
    unsigned long long acc0 = bfw_to_pk(sp.x);
    unsigned long long acc1 = bfw_to_pk(sp.y);
    if (LAYER == 1) {
        unsigned long long dd = pack2(dv, dv);
        acc0 = mul2(acc0, dd);
        acc1 = mul2(acc1, dd);
    }

    int k = beg;
    // 8-deep: 8 independent gathers in flight per iteration
    for (; k + 7 < end; k += 8) {
        int sx[8];
#pragma unroll
        for (int u = 0; u < 8; u++) sx[u] = g_csr[k + u];
        uint2 px[8];
#pragma unroll
        for (int u = 0; u < 8; u++) px[u] = hv[sx[u] * 32 + lane];
        if (LAYER == 1) {
            float dx[8];
#pragma unroll
            for (int u = 0; u < 8; u++) dx[u] = __ldg(&g_dinv[sx[u]]);
#pragma unroll
            for (int u = 0; u < 8; u++) {
                unsigned long long dd = pack2(dx[u], dx[u]);
                acc0 = fma2(bfw_to_pk(px[u].x), dd, acc0);
                acc1 = fma2(bfw_to_pk(px[u].y), dd, acc1);
            }
        } else {
#pragma unroll
            for (int u = 0; u < 8; u++) {
                acc0 = add2(bfw_to_pk(px[u].x), acc0);
                acc1 = add2(bfw_to_pk(px[u].y), acc1);
            }
        }
    }
    // remainder
    for (; k < end; k++) {
        int s = g_csr[k];
        uint2 p = hv[s * 32 + lane];
        if (LAYER == 1) {
            float d = __ldg(&g_dinv[s]);
            unsigned long long dd = pack2(d, d);
            acc0 = fma2(bfw_to_pk(p.x), dd, acc0);
            acc1 = fma2(bfw_to_pk(p.y), dd, acc1);
        } else {
            acc0 = add2(bfw_to_pk(p.x), acc0);
            acc1 = add2(bfw_to_pk(p.y), acc1);
        }
    }

    float4 acc;
    unpack2(acc0, acc.x, acc.y);
    unpack2(acc1, acc.z, acc.w);

    if (LAYER == 1) {
        float4 bb = ((const float4*)bias)[lane];
        float4 r;
        r.x = fmaf(dv, acc.x, bb.x);
        r.y = fmaf(dv, acc.y, bb.y);
        r.z = fmaf(dv, acc.z, bb.z);
        r.w = fmaf(dv, acc.w, bb.w);
        r.x = fmaxf(r.x, 0.f) * dv;
        r.y = fmaxf(r.y, 0.f) * dv;
        r.z = fmaxf(r.z, 0.f) * dv;
        r.w = fmaxf(r.w, 0.f) * dv;
        ((uint2*)g_x2b)[w * 32 + lane] = f4_to_bf4(r);
    } else {
        float4 r = make_float4(dv * acc.x, dv * acc.y, dv * acc.z, dv * acc.w);
        ((float4*)g_y)[w * 32 + lane] = r;
    }
}

// ---------------- fused pool + out-GEMM: one block per graph ----------------
// out[g] = mean_{i in graph g}(y_i) @ W2 + b2   (empty graph -> 0)
__device__ __forceinline__ int lower_bound_dev(const int* a, int n, int key) {
    int lo = 0, hi = n;
    while (lo < hi) {
        int mid = (lo + hi) >> 1;
        if (a[mid] < key) lo = mid + 1; else hi = mid;
    }
    return lo;
}

__global__ void __launch_bounds__(512) poolout_kernel(const int* __restrict__ batch,
                                                      const float* __restrict__ W2,
                                                      const float* __restrict__ b2,
                                                      float* __restrict__ out) {
    __shared__ float zrow[128];
    __shared__ float red[4][128];
    __shared__ int s_lo, s_hi;
    int g = blockIdx.x;
    int t = threadIdx.x;
    int f   = t & 127;   // feature
    int seg = t >> 7;    // slice 0..3
    if (t == 0) {
        s_lo = lower_bound_dev(batch, NN, g);
        s_hi = lower_bound_dev(batch, NN, g + 1);
    }
    __syncthreads();
    int lo = s_lo, hi = s_hi;
    // pool
    float sum = 0.f;
    for (int r = lo + seg; r < hi; r += 4) sum += g_y[r * 128 + f];
    red[seg][f] = sum;
    __syncthreads();
    if (seg == 0) {
        float c = (float)(hi - lo);
        zrow[f] = (red[0][f] + red[1][f] + red[2][f] + red[3][f]) / fmaxf(c, 1.0f);
    }
    __syncthreads();
    // gemm: 4-way k-split dot with W2
    float acc = 0.f;
    int k0 = seg * 32;
#pragma unroll
    for (int kk = 0; kk < 32; kk++) {
        int k = k0 + kk;
        acc = fmaf(zrow[k], W2[k * 128 + f], acc);
    }
    red[seg][f] = acc;
    __syncthreads();
    if (seg == 0) {
        float r = (hi > lo)
                ? (red[0][f] + red[1][f] + red[2][f] + red[3][f] + b2[f])
                : 0.0f;   // empty graph: reference yields exactly 0
        out[g * 128 + f] = r;
    }
}

// ---------------- launch ----------------
extern "C" void kernel_launch(void* const* d_in, const int* in_sizes, int n_in,
                              void* d_out, int out_size) {
    const float* x     = (const float*)d_in[0];
    const int*   ei    = (const int*)d_in[1];   // [2, E] row-major
    const int*   batch = (const int*)d_in[2];
    const float* W1    = (const float*)d_in[3];
    const float* b1    = (const float*)d_in[4];
    const float* W2    = (const float*)d_in[5];
    const float* b2    = (const float*)d_in[6];
    float* out = (float*)d_out;

    const int* src = ei;        // edge_index[0]
    const int* dst = ei + NE;   // edge_index[1]

    // One-time host resources (streams/events are not device memory).
    static cudaStream_t s2 = nullptr;
    static cudaEvent_t evFork = nullptr, evJoin = nullptr;
    if (s2 == nullptr) {
        cudaStreamCreateWithFlags(&s2, cudaStreamNonBlocking);
        cudaEventCreateWithFlags(&evFork, cudaEventDisableTiming);
        cudaEventCreateWithFlags(&evJoin, cudaEventDisableTiming);
    }

    // Fork: GEMM-1 (no dependence on edges/dinv) runs on s2 while the CSR
    // build runs on the main stream.
    cudaEventRecord(evFork, 0);
    cudaStreamWaitEvent(s2, evFork, 0);
    gemm_kernel<<<(NN + 127) / 128, 256, 0, s2>>>(x, W1);
    cudaEventRecord(evJoin, s2);

    // CSR build (by destination) + dinv. g_deg and g_flagv are zero on entry
    // (zero-init on first call; re-zeroed by agg1 on every call).
    hist_kernel<<<(NE + 255) / 256, 256>>>(dst);
    scan_kernel<<<NSCAN, SCAN_B>>>();
    fill_kernel<<<(NE + 255) / 256, 256>>>(src, dst);

    // Join: aggregation needs both GEMM-1 output and the CSR.
    cudaStreamWaitEvent(0, evJoin, 0);

    // Layer 1 aggregation (+relu, +b1), writes dinv-prescaled bf16 x2.
    agg_kernel<1><<<(NN + 7) / 8, 256>>>(b1);

    // Layer 2 aggregation only (W2 commuted past S and pooling), writes g_y.
    agg_kernel<2><<<(NN + 7) / 8, 256>>>(nullptr);

    // Fused global-mean-pool + (z @ W2 + b2)
    poolout_kernel<<<NG, 512>>>(batch, W2, b2, out);
}